// round 4
// baseline (speedup 1.0000x reference)
#include <cuda_runtime.h>
#include <math.h>

#define BATCH 32
#define NCLS 3
#define HH 192
#define WW 640
#define HW (HH*WW)
#define NPL (BATCH*NCLS)
#define KTOP 50
#define NEG_INF -3.402823466e38f
#define PI_F 3.14159265358979f
#define DET_THR 0.25f
#define RROWS 8
#define NYB (HH/RROWS)
#define CCAP 512
#define TCAP 8
#define NTHR 160

typedef unsigned long long u64;
typedef unsigned int u32;

// -------- scratch (static device globals; zero-initialized at load) --------
__device__ int g_count[NPL];
__device__ int g_plane_arrive[NPL];
__device__ int g_batch_arrive[BATCH];
__device__ u64 g_ckey[NPL][HW];          // packed (val_bits<<32 | ~idx)
__device__ u64 g_topk[NPL][KTOP];

__constant__ float c_dimref[3][3] = {
    {3.88f, 1.63f, 1.53f},
    {0.84f, 1.76f, 0.66f},
    {1.78f, 1.52f, 1.78f}};

__device__ __forceinline__ float max3(float a, float b, float c) {
    return fmaxf(a, fmaxf(b, c));
}
__device__ __forceinline__ u64 pack_key(float v, int idx) {
    return ((u64)__float_as_uint(v) << 32) | (u32)(~idx);
}
__device__ __forceinline__ void inv3(const float* M, float* R) {
    float a = M[0], b = M[1], c = M[2];
    float d = M[3], e = M[4], f = M[5];
    float g = M[6], h = M[7], i = M[8];
    float A = e * i - f * h;
    float Bm = -(d * i - f * g);
    float C = d * h - e * g;
    float det = a * A + b * Bm + c * C;
    float id = 1.0f / det;
    R[0] = A * id;  R[1] = -(b * i - c * h) * id;  R[2] = (b * f - c * e) * id;
    R[3] = Bm * id; R[4] = (a * i - c * g) * id;   R[5] = -(a * f - c * d) * id;
    R[6] = C * id;  R[7] = -(a * h - b * g) * id;  R[8] = (a * e - b * d) * id;
}

// =============== single fused kernel ===============
// Stage 1 (all 2304 blocks): rolling-window 3x3 NMS, distance-2 prefetch,
//   per-thread smem staging (provable cap 8), one block scan + one atomic.
// Stage 2 (last block per plane): histogram-threshold exact top-50.
// Stage 3 (last plane per batch): merge 150 -> 50 + detection math.
__global__ __launch_bounds__(NTHR, 8) void k_fused(
    const float* __restrict__ heat, const float* __restrict__ reg,
    const float* __restrict__ tmat, const float* __restrict__ Kmat,
    const float* __restrict__ img, float* __restrict__ out) {

    int plane = blockIdx.y;
    int tid = threadIdx.x;
    int warp = tid >> 5, lane = tid & 31;
    int xb = warp * 128 + lane * 4;
    int y0 = blockIdx.x * RROWS;
    const float* p = heat + (size_t)plane * HW;
    bool hasL = (xb > 0), hasR = (xb + 4 < WW);
    bool eL = (lane == 0) && hasL;
    bool eR = (lane == 31) && hasR;

    __shared__ u64 sbuf[TCAP][NTHR];
    __shared__ int wtot[5], spref[5];
    __shared__ int sgbase;
    __shared__ int sflag;

    const float4 NEG4 = make_float4(NEG_INF, NEG_INF, NEG_INF, NEG_INF);

    // ---- stage 1: NMS ----
    const float* row = p + y0 * WW + xb;
    float4 a = (y0 > 0) ? *(const float4*)(row - WW) : NEG4;
    float4 b = *(const float4*)row;
    float4 c = *(const float4*)(row + WW);           // y0+1 <= 185 < 192 always
    float la0 = (eL && y0 > 0) ? row[-WW - 1] : NEG_INF;
    float la1 = eL ? row[-1] : NEG_INF;
    float la2 = eL ? row[WW - 1] : NEG_INF;
    float ra0 = (eR && y0 > 0) ? row[-WW + 4] : NEG_INF;
    float ra1 = eR ? row[4] : NEG_INF;
    float ra2 = eR ? row[WW + 4] : NEG_INF;
    const float* nrow = row + 2 * WW;                // prefetch pointer: row y0+2

    int cnt = 0;
#pragma unroll
    for (int r = 0; r < RROWS; r++) {
        int y = y0 + r;
        bool nv = (y + 2 < HH);
        float4 d = nv ? *(const float4*)nrow : NEG4;             // prefetch y+2
        float la3 = (eL && nv) ? nrow[-1] : NEG_INF;
        float ra3 = (eR && nv) ? nrow[4] : NEG_INF;
        nrow += WW;

        float4 cm;
        cm.x = max3(a.x, b.x, c.x);
        cm.y = max3(a.y, b.y, c.y);
        cm.z = max3(a.z, b.z, c.z);
        cm.w = max3(a.w, b.w, c.w);
        float lmx = max3(la0, la1, la2);
        float rmx = max3(ra0, ra1, ra2);

        float left = __shfl_up_sync(0xffffffffu, cm.w, 1);
        if (lane == 0) left = lmx;
        float right = __shfl_down_sync(0xffffffffu, cm.x, 1);
        if (lane == 31) right = rmx;

        float h0 = max3(left, cm.x, cm.y);
        float h1 = max3(cm.x, cm.y, cm.z);
        float h2 = max3(cm.y, cm.z, cm.w);
        float h3 = max3(cm.z, cm.w, right);

        int bi = y * WW + xb;
        // survivors: hmax(3x3 incl self)==val, score>thr (exact: <=thr rows
        // are zeroed in the output and can't displace >thr candidates).
        // Strict local maxima are >=2 apart => <=8 per 4x8 strip => TCAP=8 safe.
        if (h0 == b.x && b.x > DET_THR && cnt < TCAP) sbuf[cnt++][tid] = pack_key(b.x, bi);
        if (h1 == b.y && b.y > DET_THR && cnt < TCAP) sbuf[cnt++][tid] = pack_key(b.y, bi + 1);
        if (h2 == b.z && b.z > DET_THR && cnt < TCAP) sbuf[cnt++][tid] = pack_key(b.z, bi + 2);
        if (h3 == b.w && b.w > DET_THR && cnt < TCAP) sbuf[cnt++][tid] = pack_key(b.w, bi + 3);

        a = b; b = c; c = d;
        la0 = la1; la1 = la2; la2 = la3;
        ra0 = ra1; ra1 = ra2; ra2 = ra3;
    }

    // one block-wide compaction (warp scan of per-thread counts)
    int x = cnt;
#pragma unroll
    for (int off = 1; off < 32; off <<= 1) {
        int yv = __shfl_up_sync(0xffffffffu, x, off);
        if (lane >= off) x += yv;
    }
    int excl = x - cnt;
    if (lane == 31) wtot[warp] = x;
    __syncthreads();
    if (tid == 0) {
        int s = 0;
#pragma unroll
        for (int w = 0; w < 5; w++) { spref[w] = s; s += wtot[w]; }
        sgbase = (s > 0) ? atomicAdd(&g_count[plane], s) : 0;
    }
    __syncthreads();
    int base = sgbase + spref[warp] + excl;
    for (int j = 0; j < cnt; j++)
        g_ckey[plane][base + j] = sbuf[j][tid];

    // ---- arrival: last block of this plane proceeds to top-k ----
    __threadfence();
    __syncthreads();
    if (tid == 0) {
        int old = atomicAdd(&g_plane_arrive[plane], 1);
        sflag = (old == NYB - 1);
        if (sflag) g_plane_arrive[plane] = 0;   // reset for next replay
    }
    __syncthreads();
    if (!sflag) return;
    __threadfence();

    // ---- stage 2: per-plane exact top-50 via histogram threshold ----
    __shared__ int hist[1024];
    __shared__ u64 cand[CCAP];
    __shared__ int sB, sccount, sn;

    if (tid == 0) {
        sn = g_count[plane];
        g_count[plane] = 0;
        sccount = 0;
    }
    for (int i = tid; i < 1024; i += NTHR) hist[i] = 0;
    __syncthreads();

    int n = sn;
    const u64* ck = g_ckey[plane];

    for (int i = tid; i < n; i += NTHR) {
        u32 vb = (u32)(ck[i] >> 32);
        int bkt = (int)((vb - 0x3e800000u) >> 14);
        if (bkt > 1023) bkt = 1023;
        atomicAdd(&hist[bkt], 1);
    }
    __syncthreads();
    if (tid == 0) {
        int cum = 0, bsel = 0;
        for (int bkt = 1023; bkt >= 0; bkt--) {
            cum += hist[bkt];
            if (cum >= KTOP) { bsel = bkt; break; }
        }
        sB = bsel;
    }
    __syncthreads();
    u64 kmin = ((u64)(0x3e800000u + ((u32)sB << 14))) << 32;

    for (int i = tid; i < n; i += NTHR) {
        u64 k = ck[i];
        if (k >= kmin) {
            int pos = atomicAdd(&sccount, 1);
            if (pos < CCAP) cand[pos] = k;
        }
    }
    if (tid < KTOP) g_topk[plane][tid] = 0;   // padding when <50 candidates
    __syncthreads();

    int m = min(sccount, CCAP);
    for (int i = tid; i < m; i += NTHR) {
        u64 k = cand[i];
        int rank = 0;
        for (int j = 0; j < m; j++) rank += (cand[j] > k);
        if (rank < KTOP) g_topk[plane][rank] = k;
    }

    // ---- arrival: last plane of this batch proceeds to final math ----
    int bb = plane / NCLS;
    __threadfence();
    __syncthreads();
    if (tid == 0) {
        int old = atomicAdd(&g_batch_arrive[bb], 1);
        sflag = (old == NCLS - 1);
        if (sflag) g_batch_arrive[bb] = 0;
    }
    __syncthreads();
    if (!sflag) return;
    __threadfence();

    // ---- stage 3: merge 150 -> 50 + detection math ----
    __shared__ float sv[150];

    float score = 0.0f;
    int ind = 0;
    float r8[8];

    if (tid < 150) {
        u64 k = g_topk[bb * NCLS + tid / KTOP][tid % KTOP];
        score = __uint_as_float((u32)(k >> 32));
        ind = (int)(~(u32)k);
        if ((unsigned)ind >= HW) ind = 0;
        sv[tid] = score;
#pragma unroll
        for (int ch = 0; ch < 8; ch++)
            r8[ch] = reg[((size_t)bb * 8 + ch) * HW + ind];
    }
    __syncthreads();
    if (tid >= 150) return;

    float mv = sv[tid];
    int rank = 0;
    for (int j = 0; j < 150; j++) {
        float o = sv[j];
        if (o > mv || (o == mv && j < tid)) rank++;
    }
    if (rank >= KTOP) return;

    float* o = out + ((size_t)bb * KTOP + rank) * 14;

    if (!(score > DET_THR)) {
#pragma unroll
        for (int k = 0; k < 14; k++) o[k] = 0.0f;
        return;
    }

    int cls = tid / KTOP;
    float xs = (float)(ind % WW);
    float ys = (float)(ind / WW);

    float T[9], Ti[9], Kk[9], Ki[9];
#pragma unroll
    for (int k = 0; k < 9; k++) { T[k] = tmat[bb * 9 + k]; Kk[k] = Kmat[bb * 9 + k]; }
    inv3(T, Ti);
    inv3(Kk, Ki);

    float px = xs + r8[1];
    float py = ys + r8[2];
    float pix = Ti[0] * px + Ti[1] * py + Ti[2];
    float piy = Ti[3] * px + Ti[4] * py + Ti[5];
    float piz = Ti[6] * px + Ti[7] * py + Ti[8];

    float depth = r8[0] * 16.32f + 28.01f;
    float vx = pix * depth, vy = piy * depth, vz = piz * depth;
    float lx = Ki[0] * vx + Ki[1] * vy + Ki[2] * vz;
    float ly = Ki[3] * vx + Ki[4] * vy + Ki[5] * vz;
    float lz = Ki[6] * vx + Ki[7] * vy + Ki[8] * vz;

    float d0 = __expf(r8[3]) * c_dimref[cls][0];
    float d1 = __expf(r8[4]) * c_dimref[cls][1];
    float d2 = __expf(r8[5]) * c_dimref[cls][2];
    ly += d1 * 0.5f;

    float rays = atanf(__fdividef(lx, lz + 1e-7f));
    float al = atanf(__fdividef(r8[6], r8[7] + 1e-7f));
    al += (r8[7] >= 0.0f) ? -PI_F * 0.5f : PI_F * 0.5f;
    float roty = al + rays;
    roty = (roty > PI_F) ? roty - 2.0f * PI_F : ((roty < -PI_F) ? roty + 2.0f * PI_F : roty);
    al   = (al   > PI_F) ? al   - 2.0f * PI_F : ((al   < -PI_F) ? al   + 2.0f * PI_F : al);

    const float SX[8] = {-0.5f, 0.5f, 0.5f, 0.5f, 0.5f, -0.5f, -0.5f, -0.5f};
    const float SY[8] = {-1.0f, -1.0f, 0.0f, 0.0f, -1.0f, -1.0f, 0.0f, 0.0f};
    const float SZ[8] = {-0.5f, -0.5f, -0.5f, 0.5f, 0.5f, 0.5f, 0.5f, -0.5f};

    float sr, cr;
    __sincosf(roty, &sr, &cr);
    float umin = 3.4e38f, umax = -3.4e38f, wmin = 3.4e38f, wmax = -3.4e38f;
#pragma unroll
    for (int j = 0; j < 8; j++) {
        float cx = d0 * SX[j], cy = d1 * SY[j], cz = d2 * SZ[j];
        float wx = cr * cx + sr * cz + lx;
        float wy = cy + ly;
        float wz = -sr * cx + cr * cz + lz;
        float qx = Kk[0] * wx + Kk[1] * wy + Kk[2] * wz;
        float qy = Kk[3] * wx + Kk[4] * wy + Kk[5] * wz;
        float qz = Kk[6] * wx + Kk[7] * wy + Kk[8] * wz;
        float rq = __fdividef(1.0f, qz);
        float u = qx * rq;
        float w = qy * rq;
        umin = fminf(umin, u); umax = fmaxf(umax, u);
        wmin = fminf(wmin, w); wmax = fmaxf(wmax, w);
    }

    float Wi = img[bb * 2 + 0], Hi = img[bb * 2 + 1];
    float xmin = fminf(fmaxf(umin, 0.0f), Wi);
    float ymin = fminf(fmaxf(wmin, 0.0f), Hi);
    float xmax = fminf(fmaxf(umax, 0.0f), Wi);
    float ymax = fminf(fmaxf(wmax, 0.0f), Hi);

    o[0]  = (float)cls;
    o[1]  = al;
    o[2]  = xmin;
    o[3]  = ymin;
    o[4]  = xmax;
    o[5]  = ymax;
    o[6]  = d1;   // dims rolled -1: (d1, d2, d0)
    o[7]  = d2;
    o[8]  = d0;
    o[9]  = lx;
    o[10] = ly;
    o[11] = lz;
    o[12] = roty;
    o[13] = score;
}

extern "C" void kernel_launch(void* const* d_in, const int* in_sizes, int n_in,
                              void* d_out, int out_size) {
    const float* heat = (const float*)d_in[0];
    const float* reg  = (const float*)d_in[1];
    const float* tm   = (const float*)d_in[2];
    const float* Km   = (const float*)d_in[3];
    const float* img  = (const float*)d_in[4];
    float* out = (float*)d_out;

    dim3 grid(NYB, NPL);   // 24 x 96
    k_fused<<<grid, NTHR>>>(heat, reg, tm, Km, img, out);
}

// round 5
// speedup vs baseline: 1.4436x; 1.4436x over previous
#include <cuda_runtime.h>
#include <math.h>

#define BATCH 32
#define NCLS 3
#define HH 192
#define WW 640
#define HW (HH*WW)
#define NPL (BATCH*NCLS)
#define KTOP 50
#define NEG_INF -3.402823466e38f
#define PI_F 3.14159265358979f
#define DET_THR 0.25f
#define RROWS 8
#define NYB (HH/RROWS)
#define CCAP 1024
#define TCAP 8
#define NTHR 160

typedef unsigned long long u64;
typedef unsigned int u32;

// -------- scratch (static device globals; zero-initialized at load) --------
__device__ int g_count[NPL];
__device__ u64 g_ckey[NPL][HW];          // packed (val_bits<<32 | ~idx)
__device__ u64 g_topk[NPL][KTOP];

__constant__ float c_dimref[3][3] = {
    {3.88f, 1.63f, 1.53f},
    {0.84f, 1.76f, 0.66f},
    {1.78f, 1.52f, 1.78f}};

__device__ __forceinline__ float max3(float a, float b, float c) {
    return fmaxf(a, fmaxf(b, c));
}
__device__ __forceinline__ u64 pack_key(float v, int idx) {
    return ((u64)__float_as_uint(v) << 32) | (u32)(~idx);
}

// -------- pass 1: 3x3 NMS, load-all-then-compute (MLP=10) --------
// Block = 160 threads = 5 warps spanning the full 640-px row width, so every
// horizontal neighbor is inside the block: boundary column-maxes exchanged
// through smem, ZERO edge scalar loads. Each thread loads its 10 rows up
// front (10 independent LDG.128 in flight), then computes. Survivors stage
// into per-thread smem slots (strict 3x3 maxima are >=2 apart => <=8 per
// 4x8 strip); one block scan + one global atomic per block.
__global__ __launch_bounds__(NTHR) void k_nms(const float* __restrict__ heat) {
    int plane = blockIdx.y;
    int tid = threadIdx.x;
    int warp = tid >> 5, lane = tid & 31;
    int xb = warp * 128 + lane * 4;
    int y0 = blockIdx.x * RROWS;
    const float* p = heat + (size_t)plane * HW + xb;

    const float4 NEG4 = make_float4(NEG_INF, NEG_INF, NEG_INF, NEG_INF);

    __shared__ float sL[5][RROWS];    // lane31 cm.w per warp/row
    __shared__ float sR[5][RROWS];    // lane0  cm.x per warp/row
    __shared__ u64 sbuf[TCAP][NTHR];
    __shared__ int wtot[5], spref[5];
    __shared__ int sgbase;

    // ---- load all 10 rows (y0-1 .. y0+8) up front: MLP = 10 ----
    float4 r[RROWS + 2];
    const float* rp = p + (y0 - 1) * WW;
#pragma unroll
    for (int k = 0; k < RROWS + 2; k++) {
        int y = y0 - 1 + k;
        r[k] = (y >= 0 && y < HH) ? *(const float4*)(rp + k * WW) : NEG4;
    }

    // ---- vertical column maxes ----
    float4 cm[RROWS];
#pragma unroll
    for (int i = 0; i < RROWS; i++) {
        cm[i].x = max3(r[i].x, r[i+1].x, r[i+2].x);
        cm[i].y = max3(r[i].y, r[i+1].y, r[i+2].y);
        cm[i].z = max3(r[i].z, r[i+1].z, r[i+2].z);
        cm[i].w = max3(r[i].w, r[i+1].w, r[i+2].w);
    }

    // ---- cross-warp boundary exchange (replaces global edge loads) ----
    if (lane == 31) {
#pragma unroll
        for (int i = 0; i < RROWS; i++) sL[warp][i] = cm[i].w;
    }
    if (lane == 0) {
#pragma unroll
        for (int i = 0; i < RROWS; i++) sR[warp][i] = cm[i].x;
    }
    __syncthreads();

    int cnt = 0;
#pragma unroll
    for (int i = 0; i < RROWS; i++) {
        float left = __shfl_up_sync(0xffffffffu, cm[i].w, 1);
        if (lane == 0) left = (warp > 0) ? sL[warp - 1][i] : NEG_INF;
        float right = __shfl_down_sync(0xffffffffu, cm[i].x, 1);
        if (lane == 31) right = (warp < 4) ? sR[warp + 1][i] : NEG_INF;

        float h0 = max3(left,    cm[i].x, cm[i].y);
        float h1 = max3(cm[i].x, cm[i].y, cm[i].z);
        float h2 = max3(cm[i].y, cm[i].z, cm[i].w);
        float h3 = max3(cm[i].z, cm[i].w, right);

        float4 b = r[i + 1];
        int bi = (y0 + i) * WW + xb;
        // survivors: hmax(3x3 incl self)==val, score>thr (exact: <=thr rows
        // are zeroed in the output and can't displace >thr candidates)
        if (h0 == b.x && b.x > DET_THR && cnt < TCAP) sbuf[cnt++][tid] = pack_key(b.x, bi);
        if (h1 == b.y && b.y > DET_THR && cnt < TCAP) sbuf[cnt++][tid] = pack_key(b.y, bi + 1);
        if (h2 == b.z && b.z > DET_THR && cnt < TCAP) sbuf[cnt++][tid] = pack_key(b.z, bi + 2);
        if (h3 == b.w && b.w > DET_THR && cnt < TCAP) sbuf[cnt++][tid] = pack_key(b.w, bi + 3);
    }

    // ---- one block-wide compaction ----
    int x = cnt;
#pragma unroll
    for (int off = 1; off < 32; off <<= 1) {
        int yv = __shfl_up_sync(0xffffffffu, x, off);
        if (lane >= off) x += yv;
    }
    int excl = x - cnt;
    if (lane == 31) wtot[warp] = x;
    __syncthreads();
    if (tid == 0) {
        int s = 0;
#pragma unroll
        for (int w = 0; w < 5; w++) { spref[w] = s; s += wtot[w]; }
        sgbase = (s > 0) ? atomicAdd(&g_count[plane], s) : 0;
    }
    __syncthreads();
    int base = sgbase + spref[warp] + excl;
    for (int j = 0; j < cnt; j++)
        g_ckey[plane][base + j] = sbuf[j][tid];
}

// -------- pass 2: per-plane exact top-50 via histogram threshold --------
__global__ __launch_bounds__(1024) void k_planetop() {
    int plane = blockIdx.x;
    int tid = threadIdx.x;

    __shared__ int hist[1024];
    __shared__ int sn, sB, sccount;
    __shared__ u64 cand[CCAP];

    if (tid == 0) {
        sn = g_count[plane];
        g_count[plane] = 0;   // reset for next graph replay
        sccount = 0;
    }
    hist[tid] = 0;
    __syncthreads();

    int n = sn;
    const u64* ck = g_ckey[plane];

    // pass A: histogram of value bits (monotonic buckets over (0.25, 1.0+])
    for (int i = tid; i < n; i += 1024) {
        u32 vb = (u32)(ck[i] >> 32);
        int bkt = (int)((vb - 0x3e800000u) >> 14);
        if (bkt > 1023) bkt = 1023;
        atomicAdd(&hist[bkt], 1);
    }
    __syncthreads();

    if (tid == 0) {
        int cum = 0, bsel = 0;
        for (int bkt = 1023; bkt >= 0; bkt--) {
            cum += hist[bkt];
            if (cum >= KTOP) { bsel = bkt; break; }
        }
        sB = bsel;
    }
    __syncthreads();

    u64 kmin = ((u64)(0x3e800000u + ((u32)sB << 14))) << 32;

    // pass B: compact candidates >= bucket threshold (~50-70 expected)
    for (int i = tid; i < n; i += 1024) {
        u64 k = ck[i];
        if (k >= kmin) {
            int pos = atomicAdd(&sccount, 1);
            if (pos < CCAP) cand[pos] = k;
        }
    }
    if (tid < KTOP) g_topk[plane][tid] = 0;   // padding when <50 candidates
    __syncthreads();

    int m = min(sccount, CCAP);
    if (tid < m) {
        u64 k = cand[tid];
        int rank = 0;
        for (int j = 0; j < m; j++) rank += (cand[j] > k);
        if (rank < KTOP) g_topk[plane][rank] = k;
    }
}

// -------- pass 3: per-batch top-50 of 150 + full detection math --------
__device__ __forceinline__ void inv3(const float* M, float* R) {
    float a = M[0], b = M[1], c = M[2];
    float d = M[3], e = M[4], f = M[5];
    float g = M[6], h = M[7], i = M[8];
    float A = e * i - f * h;
    float Bm = -(d * i - f * g);
    float C = d * h - e * g;
    float det = a * A + b * Bm + c * C;
    float id = 1.0f / det;
    R[0] = A * id;  R[1] = -(b * i - c * h) * id;  R[2] = (b * f - c * e) * id;
    R[3] = Bm * id; R[4] = (a * i - c * g) * id;   R[5] = -(a * f - c * d) * id;
    R[6] = C * id;  R[7] = -(a * h - b * g) * id;  R[8] = (a * e - b * d) * id;
}

__global__ __launch_bounds__(160) void k_final(const float* __restrict__ reg,
                        const float* __restrict__ tmat,
                        const float* __restrict__ Kmat,
                        const float* __restrict__ img,
                        float* __restrict__ out) {
    int b = blockIdx.x;
    int tid = threadIdx.x;

    __shared__ float sv[150];

    float score = 0.0f;
    int ind = 0;
    float r8[8];

    if (tid < 150) {
        u64 k = g_topk[b * NCLS + tid / KTOP][tid % KTOP];
        score = __uint_as_float((u32)(k >> 32));
        ind = (int)(~(u32)k);
        if ((unsigned)ind >= HW) ind = 0;
        sv[tid] = score;
        // gather 8 reg channels (MLP=8; overlaps ranking below)
#pragma unroll
        for (int ch = 0; ch < 8; ch++)
            r8[ch] = reg[((size_t)b * 8 + ch) * HW + ind];
    }
    __syncthreads();

    if (tid >= 150) return;

    // rank among 150 (stable: value desc, position asc) — exact lax.top_k order
    float mv = sv[tid];
    int rank = 0;
    for (int j = 0; j < 150; j++) {
        float o = sv[j];
        if (o > mv || (o == mv && j < tid)) rank++;
    }
    if (rank >= KTOP) return;

    float* o = out + ((size_t)b * KTOP + rank) * 14;

    if (!(score > DET_THR)) {
#pragma unroll
        for (int k = 0; k < 14; k++) o[k] = 0.0f;
        return;
    }

    int cls = tid / KTOP;
    float xs = (float)(ind % WW);
    float ys = (float)(ind / WW);

    float T[9], Ti[9], Kk[9], Ki[9];
#pragma unroll
    for (int k = 0; k < 9; k++) { T[k] = tmat[b * 9 + k]; Kk[k] = Kmat[b * 9 + k]; }
    inv3(T, Ti);
    inv3(Kk, Ki);

    float px = xs + r8[1];
    float py = ys + r8[2];
    float pix = Ti[0] * px + Ti[1] * py + Ti[2];
    float piy = Ti[3] * px + Ti[4] * py + Ti[5];
    float piz = Ti[6] * px + Ti[7] * py + Ti[8];

    float depth = r8[0] * 16.32f + 28.01f;
    float vx = pix * depth, vy = piy * depth, vz = piz * depth;
    float lx = Ki[0] * vx + Ki[1] * vy + Ki[2] * vz;
    float ly = Ki[3] * vx + Ki[4] * vy + Ki[5] * vz;
    float lz = Ki[6] * vx + Ki[7] * vy + Ki[8] * vz;

    float d0 = __expf(r8[3]) * c_dimref[cls][0];
    float d1 = __expf(r8[4]) * c_dimref[cls][1];
    float d2 = __expf(r8[5]) * c_dimref[cls][2];
    ly += d1 * 0.5f;

    float rays = atanf(__fdividef(lx, lz + 1e-7f));
    float al = atanf(__fdividef(r8[6], r8[7] + 1e-7f));
    al += (r8[7] >= 0.0f) ? -PI_F * 0.5f : PI_F * 0.5f;
    float roty = al + rays;
    roty = (roty > PI_F) ? roty - 2.0f * PI_F : ((roty < -PI_F) ? roty + 2.0f * PI_F : roty);
    al   = (al   > PI_F) ? al   - 2.0f * PI_F : ((al   < -PI_F) ? al   + 2.0f * PI_F : al);

    const float SX[8] = {-0.5f, 0.5f, 0.5f, 0.5f, 0.5f, -0.5f, -0.5f, -0.5f};
    const float SY[8] = {-1.0f, -1.0f, 0.0f, 0.0f, -1.0f, -1.0f, 0.0f, 0.0f};
    const float SZ[8] = {-0.5f, -0.5f, -0.5f, 0.5f, 0.5f, 0.5f, 0.5f, -0.5f};

    float sr, cr;
    __sincosf(roty, &sr, &cr);
    float umin = 3.4e38f, umax = -3.4e38f, wmin = 3.4e38f, wmax = -3.4e38f;
#pragma unroll
    for (int j = 0; j < 8; j++) {
        float cx = d0 * SX[j], cy = d1 * SY[j], cz = d2 * SZ[j];
        float wx = cr * cx + sr * cz + lx;
        float wy = cy + ly;
        float wz = -sr * cx + cr * cz + lz;
        float qx = Kk[0] * wx + Kk[1] * wy + Kk[2] * wz;
        float qy = Kk[3] * wx + Kk[4] * wy + Kk[5] * wz;
        float qz = Kk[6] * wx + Kk[7] * wy + Kk[8] * wz;
        float rq = __fdividef(1.0f, qz);
        float u = qx * rq;
        float w = qy * rq;
        umin = fminf(umin, u); umax = fmaxf(umax, u);
        wmin = fminf(wmin, w); wmax = fmaxf(wmax, w);
    }

    float Wi = img[b * 2 + 0], Hi = img[b * 2 + 1];
    float xmin = fminf(fmaxf(umin, 0.0f), Wi);
    float ymin = fminf(fmaxf(wmin, 0.0f), Hi);
    float xmax = fminf(fmaxf(umax, 0.0f), Wi);
    float ymax = fminf(fmaxf(wmax, 0.0f), Hi);

    o[0]  = (float)cls;
    o[1]  = al;
    o[2]  = xmin;
    o[3]  = ymin;
    o[4]  = xmax;
    o[5]  = ymax;
    o[6]  = d1;   // dims rolled -1: (d1, d2, d0)
    o[7]  = d2;
    o[8]  = d0;
    o[9]  = lx;
    o[10] = ly;
    o[11] = lz;
    o[12] = roty;
    o[13] = score;
}

extern "C" void kernel_launch(void* const* d_in, const int* in_sizes, int n_in,
                              void* d_out, int out_size) {
    const float* heat = (const float*)d_in[0];
    const float* reg  = (const float*)d_in[1];
    const float* tm   = (const float*)d_in[2];
    const float* Km   = (const float*)d_in[3];
    const float* img  = (const float*)d_in[4];
    float* out = (float*)d_out;

    dim3 g_nms(NYB, NPL);   // 24 x 96
    k_nms<<<g_nms, NTHR>>>(heat);
    k_planetop<<<NPL, 1024>>>();
    k_final<<<BATCH, 160>>>(reg, tm, Km, img, out);
}